// round 1
// baseline (speedup 1.0000x reference)
#include <cuda_runtime.h>
#include <math.h>

// ---------------- scratch (device globals; no allocation allowed) ----------
// t,p,g stacked: [n][which*256 + a][l], which in {0=theta,1=phi,2=g}
__device__ float g_tpg[3ull * 16 * 256 * 1024];     // 48 MB
__device__ float g_attn[16ull * 256 * 1024];        // 16 MB
__device__ float g_partm[16 * 64];
__device__ float g_parts[16 * 64];
__device__ float g_M[16];
__device__ float g_invZ[16];

#define LDIM 1024
#define CDIM 256
#define NB   16

// =====================================================================
// K1: fused theta/phi/g : out[m][l] = sum_k Wsel[a][k] * x[n][k][l]
//   M=768 (3*256), N=1024, K=256.  128x128x8 tile, 8x8 per thread.
// =====================================================================
__global__ __launch_bounds__(256) void k_tpg(const float* __restrict__ x,
                                             const float* __restrict__ wt,
                                             const float* __restrict__ wp,
                                             const float* __restrict__ wg) {
    __shared__ float As[8][128];
    __shared__ float Bs[8][128];
    const int n  = blockIdx.z;
    const int m0 = blockIdx.y * 128;
    const int l0 = blockIdx.x * 128;
    const float* xn = x + (size_t)n * CDIM * LDIM;

    const int tid  = threadIdx.x;
    const int row0 = (tid >> 4) * 8;
    const int col0 = (tid & 15) * 8;
    const int am  = tid >> 1, ak4 = (tid & 1) * 4;   // A: transpose-load
    const int bk  = tid >> 5, bn4 = (tid & 31) * 4;  // B: direct float4

    const int m = m0 + am;
    const float* wsel = (m < 256) ? wt : ((m < 512) ? wp : wg);
    const int a = m & 255;

    float acc[8][8];
#pragma unroll
    for (int r = 0; r < 8; r++)
#pragma unroll
        for (int c = 0; c < 8; c++) acc[r][c] = 0.f;

    for (int k0 = 0; k0 < CDIM; k0 += 8) {
        float4 av = *(const float4*)(wsel + a * CDIM + k0 + ak4);
        As[ak4 + 0][am] = av.x; As[ak4 + 1][am] = av.y;
        As[ak4 + 2][am] = av.z; As[ak4 + 3][am] = av.w;
        *(float4*)&Bs[bk][bn4] = *(const float4*)(xn + (size_t)(k0 + bk) * LDIM + l0 + bn4);
        __syncthreads();
#pragma unroll
        for (int k = 0; k < 8; k++) {
            float a8[8], b8[8];
            *(float4*)a8       = *(float4*)&As[k][row0];
            *(float4*)(a8 + 4) = *(float4*)&As[k][row0 + 4];
            *(float4*)b8       = *(float4*)&Bs[k][col0];
            *(float4*)(b8 + 4) = *(float4*)&Bs[k][col0 + 4];
#pragma unroll
            for (int r = 0; r < 8; r++)
#pragma unroll
                for (int c = 0; c < 8; c++) acc[r][c] = fmaf(a8[r], b8[c], acc[r][c]);
        }
        __syncthreads();
    }
    float* out = g_tpg + ((size_t)n * 768) * LDIM;
#pragma unroll
    for (int r = 0; r < 8; r++) {
        float* o = out + (size_t)(m0 + row0 + r) * LDIM + l0 + col0;
        *(float4*)o       = *(float4*)&acc[r][0];
        *(float4*)(o + 4) = *(float4*)&acc[r][4];
    }
}

// =====================================================================
// K2: c[n][i][j] = sum_a t[n][a][i] * p[n][a][j]   (A = t^T is K-major)
//   M=N=1024, K=256.
// =====================================================================
__global__ __launch_bounds__(256) void k_c(float* __restrict__ cout) {
    __shared__ float As[8][128];
    __shared__ float Bs[8][128];
    const int n  = blockIdx.z;
    const int i0 = blockIdx.y * 128;
    const int j0 = blockIdx.x * 128;
    const float* t = g_tpg + ((size_t)n * 768 + 0)   * LDIM;
    const float* p = g_tpg + ((size_t)n * 768 + 256) * LDIM;

    const int tid  = threadIdx.x;
    const int row0 = (tid >> 4) * 8;
    const int col0 = (tid & 15) * 8;
    const int ak  = tid >> 5, am4 = (tid & 31) * 4;  // A K-major: direct float4
    const int bk  = ak,       bn4 = am4;

    float acc[8][8];
#pragma unroll
    for (int r = 0; r < 8; r++)
#pragma unroll
        for (int c = 0; c < 8; c++) acc[r][c] = 0.f;

    for (int k0 = 0; k0 < CDIM; k0 += 8) {
        *(float4*)&As[ak][am4] = *(const float4*)(t + (size_t)(k0 + ak) * LDIM + i0 + am4);
        *(float4*)&Bs[bk][bn4] = *(const float4*)(p + (size_t)(k0 + bk) * LDIM + j0 + bn4);
        __syncthreads();
#pragma unroll
        for (int k = 0; k < 8; k++) {
            float a8[8], b8[8];
            *(float4*)a8       = *(float4*)&As[k][row0];
            *(float4*)(a8 + 4) = *(float4*)&As[k][row0 + 4];
            *(float4*)b8       = *(float4*)&Bs[k][col0];
            *(float4*)(b8 + 4) = *(float4*)&Bs[k][col0 + 4];
#pragma unroll
            for (int r = 0; r < 8; r++)
#pragma unroll
                for (int c = 0; c < 8; c++) acc[r][c] = fmaf(a8[r], b8[c], acc[r][c]);
        }
        __syncthreads();
    }
    float* out = cout + (size_t)n * LDIM * LDIM;
#pragma unroll
    for (int r = 0; r < 8; r++) {
        float* o = out + (size_t)(i0 + row0 + r) * LDIM + j0 + col0;
        *(float4*)o       = *(float4*)&acc[r][0];
        *(float4*)(o + 4) = *(float4*)&acc[r][4];
    }
}

// =====================================================================
// K3a: per (n, blk) partial max + partial sum(exp(v - local_max)) over 16384 elems
// =====================================================================
__global__ __launch_bounds__(256) void k_sm_partial(const float* __restrict__ cin) {
    __shared__ float red[256];
    const int n = blockIdx.y, blk = blockIdx.x, tid = threadIdx.x;
    const float4* base = (const float4*)(cin + (size_t)n * LDIM * LDIM + (size_t)blk * 16384);

    float m = -1e30f;
#pragma unroll
    for (int it = 0; it < 16; it++) {
        float4 v = base[it * 256 + tid];
        m = fmaxf(m, fmaxf(fmaxf(v.x, v.y), fmaxf(v.z, v.w)));
    }
    red[tid] = m;
    __syncthreads();
    for (int s = 128; s > 0; s >>= 1) {
        if (tid < s) red[tid] = fmaxf(red[tid], red[tid + s]);
        __syncthreads();
    }
    const float bm = red[0];
    __syncthreads();

    float sum = 0.f;
#pragma unroll
    for (int it = 0; it < 16; it++) {
        float4 v = base[it * 256 + tid];
        sum += expf(v.x - bm) + expf(v.y - bm) + expf(v.z - bm) + expf(v.w - bm);
    }
    red[tid] = sum;
    __syncthreads();
    for (int s = 128; s > 0; s >>= 1) {
        if (tid < s) red[tid] += red[tid + s];
        __syncthreads();
    }
    if (tid == 0) {
        g_partm[n * 64 + blk] = bm;
        g_parts[n * 64 + blk] = red[0];
    }
}

// K3b: combine 64 partials per n -> global M, 1/Z
__global__ __launch_bounds__(64) void k_sm_final() {
    __shared__ float rm[64];
    __shared__ float rs[64];
    const int n = blockIdx.x, tid = threadIdx.x;
    float m = g_partm[n * 64 + tid];
    rm[tid] = m;
    __syncthreads();
    for (int s = 32; s > 0; s >>= 1) {
        if (tid < s) rm[tid] = fmaxf(rm[tid], rm[tid + s]);
        __syncthreads();
    }
    const float M = rm[0];
    __syncthreads();
    rs[tid] = g_parts[n * 64 + tid] * expf(m - M);
    __syncthreads();
    for (int s = 32; s > 0; s >>= 1) {
        if (tid < s) rs[tid] += rs[tid + s];
        __syncthreads();
    }
    if (tid == 0) { g_M[n] = M; g_invZ[n] = 1.f / rs[0]; }
}

// =====================================================================
// K4: attn[n][a][j] = invZ * sum_i g[n][a][i] * exp(c[n][i][j] - M)
//   M=256, N=1024, K=1024. exp fused into B-tile load.
// =====================================================================
__global__ __launch_bounds__(256) void k_attn(const float* __restrict__ cin) {
    __shared__ float As[8][128];
    __shared__ float Bs[8][128];
    const int n  = blockIdx.z;
    const int m0 = blockIdx.y * 128;
    const int j0 = blockIdx.x * 128;
    const float* gmat = g_tpg + ((size_t)n * 768 + 512) * LDIM;
    const float* cn   = cin + (size_t)n * LDIM * LDIM;
    const float  M    = g_M[n];
    const float  invZ = g_invZ[n];

    const int tid  = threadIdx.x;
    const int row0 = (tid >> 4) * 8;
    const int col0 = (tid & 15) * 8;
    const int am  = tid >> 1, ak4 = (tid & 1) * 4;
    const int bk  = tid >> 5, bn4 = (tid & 31) * 4;

    float acc[8][8];
#pragma unroll
    for (int r = 0; r < 8; r++)
#pragma unroll
        for (int c = 0; c < 8; c++) acc[r][c] = 0.f;

    for (int k0 = 0; k0 < LDIM; k0 += 8) {
        float4 av = *(const float4*)(gmat + (size_t)(m0 + am) * LDIM + k0 + ak4);
        As[ak4 + 0][am] = av.x; As[ak4 + 1][am] = av.y;
        As[ak4 + 2][am] = av.z; As[ak4 + 3][am] = av.w;
        float4 bv = *(const float4*)(cn + (size_t)(k0 + bk) * LDIM + j0 + bn4);
        bv.x = expf(bv.x - M); bv.y = expf(bv.y - M);
        bv.z = expf(bv.z - M); bv.w = expf(bv.w - M);
        *(float4*)&Bs[bk][bn4] = bv;
        __syncthreads();
#pragma unroll
        for (int k = 0; k < 8; k++) {
            float a8[8], b8[8];
            *(float4*)a8       = *(float4*)&As[k][row0];
            *(float4*)(a8 + 4) = *(float4*)&As[k][row0 + 4];
            *(float4*)b8       = *(float4*)&Bs[k][col0];
            *(float4*)(b8 + 4) = *(float4*)&Bs[k][col0 + 4];
#pragma unroll
            for (int r = 0; r < 8; r++)
#pragma unroll
                for (int c = 0; c < 8; c++) acc[r][c] = fmaf(a8[r], b8[c], acc[r][c]);
        }
        __syncthreads();
    }
    float* out = g_attn + (size_t)n * CDIM * LDIM;
#pragma unroll
    for (int r = 0; r < 8; r++) {
        float* o = out + (size_t)(m0 + row0 + r) * LDIM + j0 + col0;
#pragma unroll
        for (int c = 0; c < 8; c++) o[c] = acc[r][c] * invZ;
    }
}

// =====================================================================
// K5: y[n][c][j] = x[n][c][j] + sum_a w_restore[c][a] * attn[n][a][j]
//   M=256, N=1024, K=256.
// =====================================================================
__global__ __launch_bounds__(256) void k_out(const float* __restrict__ wr,
                                             const float* __restrict__ x,
                                             float* __restrict__ y) {
    __shared__ float As[8][128];
    __shared__ float Bs[8][128];
    const int n  = blockIdx.z;
    const int m0 = blockIdx.y * 128;
    const int j0 = blockIdx.x * 128;
    const float* an = g_attn + (size_t)n * CDIM * LDIM;
    const float* xn = x + (size_t)n * CDIM * LDIM;

    const int tid  = threadIdx.x;
    const int row0 = (tid >> 4) * 8;
    const int col0 = (tid & 15) * 8;
    const int am  = tid >> 1, ak4 = (tid & 1) * 4;
    const int bk  = tid >> 5, bn4 = (tid & 31) * 4;

    float acc[8][8];
#pragma unroll
    for (int r = 0; r < 8; r++)
#pragma unroll
        for (int c = 0; c < 8; c++) acc[r][c] = 0.f;

    for (int k0 = 0; k0 < CDIM; k0 += 8) {
        float4 av = *(const float4*)(wr + (size_t)(m0 + am) * CDIM + k0 + ak4);
        As[ak4 + 0][am] = av.x; As[ak4 + 1][am] = av.y;
        As[ak4 + 2][am] = av.z; As[ak4 + 3][am] = av.w;
        *(float4*)&Bs[bk][bn4] = *(const float4*)(an + (size_t)(k0 + bk) * LDIM + j0 + bn4);
        __syncthreads();
#pragma unroll
        for (int k = 0; k < 8; k++) {
            float a8[8], b8[8];
            *(float4*)a8       = *(float4*)&As[k][row0];
            *(float4*)(a8 + 4) = *(float4*)&As[k][row0 + 4];
            *(float4*)b8       = *(float4*)&Bs[k][col0];
            *(float4*)(b8 + 4) = *(float4*)&Bs[k][col0 + 4];
#pragma unroll
            for (int r = 0; r < 8; r++)
#pragma unroll
                for (int c = 0; c < 8; c++) acc[r][c] = fmaf(a8[r], b8[c], acc[r][c]);
        }
        __syncthreads();
    }
    float* yn = y + (size_t)n * CDIM * LDIM;
#pragma unroll
    for (int r = 0; r < 8; r++) {
        const int row = m0 + row0 + r;
        float* o = yn + (size_t)row * LDIM + j0 + col0;
        const float* xi = xn + (size_t)row * LDIM + j0 + col0;
#pragma unroll
        for (int c = 0; c < 8; c++) o[c] = acc[r][c] + xi[c];
    }
}

// =====================================================================
extern "C" void kernel_launch(void* const* d_in, const int* in_sizes, int n_in,
                              void* d_out, int out_size) {
    const float* x  = (const float*)d_in[0];
    const float* wt = (const float*)d_in[1];
    const float* wp = (const float*)d_in[2];
    const float* wg = (const float*)d_in[3];
    const float* wr = (const float*)d_in[4];
    float* out = (float*)d_out;
    float* c_out = out;                                   // [16,1024,1024]
    float* y_out = out + (size_t)NB * LDIM * LDIM;        // [16,256,32,32]

    // K1: t,p,g
    k_tpg<<<dim3(LDIM / 128, 768 / 128, NB), 256>>>(x, wt, wp, wg);
    // K2: c = t^T p
    k_c<<<dim3(LDIM / 128, LDIM / 128, NB), 256>>>(c_out);
    // K3: global softmax stats
    k_sm_partial<<<dim3(64, NB), 256>>>(c_out);
    k_sm_final<<<NB, 64>>>();
    // K4: attn = (1/Z) g @ exp(c - M)
    k_attn<<<dim3(LDIM / 128, CDIM / 128, NB), 256>>>(c_out);
    // K5: y = x + wr @ attn
    k_out<<<dim3(LDIM / 128, CDIM / 128, NB), 256>>>(wr, x, y_out);
}